// round 14
// baseline (speedup 1.0000x reference)
#include <cuda_runtime.h>
#include <cuda_fp16.h>
#include <math_constants.h>

#define NMAX 50000
#define EMAX 1600000
#define HD 64
#define NH 8
#define CAP 128
#define SENT_VAL -1e30f

typedef unsigned long long u64;

// ---- scratch (static device globals; no allocation allowed) ----
__device__ __align__(16)  __half g_hh[(NMAX + 1) * HD];  // +1 sentinel row (zeros)
__device__ __align__(128) float g_esrc[(NMAX + 1) * NH]; // +1 sentinel row (-1e30)
__device__ __align__(128) float g_edst[NMAX * NH];
__device__ __align__(16)  float g_xbuf[NMAX * HD];
__device__ int g_end[NMAX];                              // padded end offset per node
__device__ int g_cursor[NMAX];
__device__ __align__(16) int g_csrc[NMAX * CAP];         // buckets, entries pre-scaled by 8

// ---------------- bucket CSR construction ----------------
__global__ void zero_counts(int n) {
    int i = blockIdx.x * blockDim.x + threadIdx.x;
    if (i < n) g_cursor[i] = 0;
    if (blockIdx.x == 0) {
        if (threadIdx.x < NH) g_esrc[n * NH + threadIdx.x] = SENT_VAL;
        if (threadIdx.x < HD) g_hh[n * HD + threadIdx.x] = __float2half(0.f);
    }
}

__global__ void fill_buckets(const int* __restrict__ src, const int* __restrict__ dst,
                             int e, int n) {
    int i = blockIdx.x * blockDim.x + threadIdx.x;
    if (i < e) {
        int d = dst[i];
        int pos = atomicAdd(&g_cursor[d], 1);
        if (pos < CAP) g_csrc[d * CAP + pos] = src[i] * NH;   // pre-scaled index
    }
}

__global__ void pad_buckets(int n) {
    int i = blockIdx.x * blockDim.x + threadIdx.x;
    if (i >= n) return;
    int c = g_cursor[i];
    if (c > CAP) c = CAP;
    int ce = (c + 7) & ~7;
    int sv = n * NH;
    for (int p = c; p < ce; p++) g_csrc[i * CAP + p] = sv;
    g_end[i] = ce;
}

// ---------------- fused GEMM + attention logits ----------------
// 8 warps/block, 4 rows/warp, f32x2 packed FMA, 4-wide k-blocks:
// per 4k: 4 W-LDS.64 + 4 A-LDS.128 (broadcast) + 16 pack + 16 FFMA2 = 64 MACs.
template <int FIN>
__global__ void gemm_att(const float* __restrict__ xin,
                         const float* __restrict__ W,
                         const float* __restrict__ att, int n) {
    __shared__ float2 sW[FIN * 32];
    __shared__ float  sx[32][FIN];
    int tid = threadIdx.x;
    const float2* W2 = (const float2*)W;
    for (int i = tid; i < FIN * 32; i += 256) sW[i] = W2[i];

    int row0 = blockIdx.x * 32;
    const float* xp = xin ? xin : g_xbuf;
    for (int i = tid; i < 8 * FIN; i += 256) {
        int r = i / (FIN / 4);
        int kk = (i % (FIN / 4)) * 4;
        float4 v = make_float4(0.f, 0.f, 0.f, 0.f);
        if (row0 + r < n) v = *(const float4*)(xp + (row0 + r) * FIN + kk);
        *(float4*)(&sx[r][kk]) = v;
    }
    __syncthreads();

    int warp = tid >> 5, lane = tid & 31;
    int r0 = warp * 4;
    const u64* sW64 = (const u64*)sW;

    u64 acc[4] = {0ull, 0ull, 0ull, 0ull};
#pragma unroll 2
    for (int kb = 0; kb < FIN; kb += 4) {
        u64 w0 = sW64[(kb + 0) * 32 + lane];
        u64 w1 = sW64[(kb + 1) * 32 + lane];
        u64 w2 = sW64[(kb + 2) * 32 + lane];
        u64 w3 = sW64[(kb + 3) * 32 + lane];
#pragma unroll
        for (int r = 0; r < 4; r++) {
            float4 a = *(const float4*)(&sx[r0 + r][kb]);   // warp-broadcast LDS.128
            u64 p0, p1, p2, p3;
            asm("mov.b64 %0, {%1, %1};" : "=l"(p0) : "f"(a.x));
            asm("mov.b64 %0, {%1, %1};" : "=l"(p1) : "f"(a.y));
            asm("mov.b64 %0, {%1, %1};" : "=l"(p2) : "f"(a.z));
            asm("mov.b64 %0, {%1, %1};" : "=l"(p3) : "f"(a.w));
            asm("fma.rn.f32x2 %0, %1, %2, %0;" : "+l"(acc[r]) : "l"(p0), "l"(w0));
            asm("fma.rn.f32x2 %0, %1, %2, %0;" : "+l"(acc[r]) : "l"(p1), "l"(w1));
            asm("fma.rn.f32x2 %0, %1, %2, %0;" : "+l"(acc[r]) : "l"(p2), "l"(w2));
            asm("fma.rn.f32x2 %0, %1, %2, %0;" : "+l"(acc[r]) : "l"(p3), "l"(w3));
        }
    }

    int head = lane >> 2;
    int d = (2 * lane) & 7;
#pragma unroll
    for (int r = 0; r < 4; r++) {
        int row = row0 + r0 + r;
        float a0, a1;
        asm("mov.b64 {%0, %1}, %2;" : "=f"(a0), "=f"(a1) : "l"(acc[r]));
        float p0 = a0 * att[head * 8 + d]      + a1 * att[head * 8 + d + 1];
        float p1 = a0 * att[64 + head * 8 + d] + a1 * att[64 + head * 8 + d + 1];
        p0 += __shfl_xor_sync(0xffffffffu, p0, 1);
        p0 += __shfl_xor_sync(0xffffffffu, p0, 2);
        p1 += __shfl_xor_sync(0xffffffffu, p1, 1);
        p1 += __shfl_xor_sync(0xffffffffu, p1, 2);
        if (row < n) {
            ((__half2*)g_hh)[row * 32 + lane] = __floats2half2_rn(a0, a1);
            if ((lane & 3) == 0) {
                g_esrc[row * NH + head] = p0;
                g_edst[row * NH + head] = p1;
            }
        }
    }
}

// ---------------- agg: padded flat 8-batches, direct exp ----------------
__global__ void __launch_bounds__(256, 6) agg_kernel(const float* __restrict__ bias,
                           float* __restrict__ xout, int apply_elu, int n) {
    int wg = (blockIdx.x * blockDim.x + threadIdx.x) >> 5;
    int lane = threadIdx.x & 31;
    if (wg >= n) return;
    int head = lane >> 2;
    float ed = g_edst[wg * NH + head];
    int nb = g_end[wg] >> 3;
    const __half2* __restrict__ hh = (const __half2*)g_hh;
    const float* __restrict__ esrc = g_esrc;
    const int4* __restrict__ csrc4 = (const int4*)(g_csrc + wg * CAP);

    float s = 0.f, ax = 0.f, ay = 0.f;

    for (int b = 0; b < nb; b++) {
        int4 c0 = csrc4[2 * b];
        int4 c1 = csrc4[2 * b + 1];
        int v[8] = {c0.x, c0.y, c0.z, c0.w, c1.x, c1.y, c1.z, c1.w};  // 8*src
        float ev[8];
        __half2 hv[8];
#pragma unroll
        for (int j = 0; j < 8; j++) ev[j] = esrc[v[j] + head];
#pragma unroll
        for (int j = 0; j < 8; j++) hv[j] = hh[v[j] * 4 + lane];
#pragma unroll
        for (int j = 0; j < 8; j++) {
            float e = ev[j] + ed;
            e = e > 0.f ? e : 0.2f * e;        // leaky relu
            float p = __expf(e);               // sentinel -> exp(-huge) = 0
            float2 hf = __half22float2(hv[j]);
            s  += p;
            ax = fmaf(p, hf.x, ax);
            ay = fmaf(p, hf.y, ay);
        }
    }

    float inv = 1.f / (s + 1e-16f);
    float o0 = ax * inv + bias[2 * lane];
    float o1 = ay * inv + bias[2 * lane + 1];
    if (apply_elu) {
        o0 = o0 > 0.f ? o0 : expm1f(o0);
        o1 = o1 > 0.f ? o1 : expm1f(o1);
    }
    float* dest = xout ? xout : g_xbuf;
    ((float2*)dest)[wg * 32 + lane] = make_float2(o0, o1);
}

// ---------------- launch ----------------
extern "C" void kernel_launch(void* const* d_in, const int* in_sizes, int n_in,
                              void* d_out, int out_size) {
    const float* x  = (const float*)d_in[0];
    const int*   ei = (const int*)d_in[1];
    int n = in_sizes[0] / 128;
    int e = in_sizes[1] / 2;
    const int* src = ei;
    const int* dst = ei + e;

    const float* W[4], *att[4], *b[4];
    for (int l = 0; l < 4; l++) {
        W[l]   = (const float*)d_in[2 + 3 * l];
        att[l] = (const float*)d_in[3 + 3 * l];
        b[l]   = (const float*)d_in[4 + 3 * l];
    }

    // bucket CSR build
    zero_counts<<<(n + 255) / 256, 256>>>(n);
    fill_buckets<<<(e + 255) / 256, 256>>>(src, dst, e, n);
    pad_buckets<<<(n + 255) / 256, 256>>>(n);

    int gemm_blk = (n + 31) / 32;
    int agg_blk  = (n + 7) / 8;

    gemm_att<128><<<gemm_blk, 256>>>(x, W[0], att[0], n);
    agg_kernel<<<agg_blk, 256>>>(b[0], nullptr, 1, n);
    gemm_att<64><<<gemm_blk, 256>>>(nullptr, W[1], att[1], n);
    agg_kernel<<<agg_blk, 256>>>(b[1], nullptr, 1, n);
    gemm_att<64><<<gemm_blk, 256>>>(nullptr, W[2], att[2], n);
    agg_kernel<<<agg_blk, 256>>>(b[2], nullptr, 1, n);
    gemm_att<64><<<gemm_blk, 256>>>(nullptr, W[3], att[3], n);
    agg_kernel<<<agg_blk, 256>>>(b[3], (float*)d_out, 0, n);
}

// round 15
// speedup vs baseline: 1.5733x; 1.5733x over previous
#include <cuda_runtime.h>
#include <cuda_fp16.h>
#include <math_constants.h>

#define NMAX 50000
#define EMAX 1600000
#define HD 64
#define NH 8
#define CAP 128
#define SENT_VAL -1e30f

typedef unsigned long long u64;

// ---- scratch (static device globals; no allocation allowed) ----
__device__ __align__(16)  __half g_hh[(NMAX + 1) * HD];  // +1 sentinel row (zeros)
__device__ __align__(128) float g_esrc[(NMAX + 1) * NH]; // +1 sentinel row (-1e30)
__device__ __align__(128) float g_edst[NMAX * NH];
__device__ __align__(16)  float g_xbuf[NMAX * HD];
__device__ int g_end[NMAX];                              // padded end offset per node
__device__ int g_cursor[NMAX];
__device__ __align__(16) int g_csrc[NMAX * CAP];         // buckets, entries pre-scaled by 8

// ---------------- bucket CSR construction ----------------
__global__ void zero_counts(int n) {
    int i = blockIdx.x * blockDim.x + threadIdx.x;
    if (i < n) g_cursor[i] = 0;
    if (blockIdx.x == 0) {
        if (threadIdx.x < NH) g_esrc[n * NH + threadIdx.x] = SENT_VAL;
        if (threadIdx.x < HD) g_hh[n * HD + threadIdx.x] = __float2half(0.f);
    }
}

__global__ void fill_buckets(const int* __restrict__ src, const int* __restrict__ dst,
                             int e, int n) {
    int i = blockIdx.x * blockDim.x + threadIdx.x;
    if (i < e) {
        int d = dst[i];
        int pos = atomicAdd(&g_cursor[d], 1);
        if (pos < CAP) g_csrc[d * CAP + pos] = src[i] * NH;   // pre-scaled index
    }
}

__global__ void pad_buckets(int n) {
    int i = blockIdx.x * blockDim.x + threadIdx.x;
    if (i >= n) return;
    int c = g_cursor[i];
    if (c > CAP) c = CAP;
    int ce = (c + 7) & ~7;
    int sv = n * NH;
    for (int p = c; p < ce; p++) g_csrc[i * CAP + p] = sv;
    g_end[i] = ce;
}

// ---------------- fused GEMM + attention logits ----------------
// R13 loop structure (measured best) with ONE change: W read by LDG (L1-resident),
// no sW smem tile -> smem 49KB->17KB -> occupancy 32->64 warps/SM.
template <int FIN>
__global__ void gemm_att(const float* __restrict__ xin,
                         const float* __restrict__ W,
                         const float* __restrict__ att, int n) {
    __shared__ float sx[32][FIN];
    int tid = threadIdx.x;

    int row0 = blockIdx.x * 32;
    const float* xp = xin ? xin : g_xbuf;
    for (int i = tid; i < 8 * FIN; i += 256) {
        int r = i / (FIN / 4);
        int kk = (i % (FIN / 4)) * 4;
        float4 v = make_float4(0.f, 0.f, 0.f, 0.f);
        if (row0 + r < n) v = *(const float4*)(xp + (row0 + r) * FIN + kk);
        *(float4*)(&sx[r][kk]) = v;
    }
    __syncthreads();

    int warp = tid >> 5, lane = tid & 31;
    int r0 = warp * 4;
    const u64* __restrict__ W64 = (const u64*)W;   // [FIN][32] col-pairs

    u64 acc[4] = {0ull, 0ull, 0ull, 0ull};
#pragma unroll 8
    for (int k = 0; k < FIN; k++) {
        u64 wp = __ldg(W64 + k * 32 + lane);       // L1-hit after first touch
#pragma unroll
        for (int r = 0; r < 4; r++) {
            float a = sx[r0 + r][k];
            u64 pa;
            asm("mov.b64 %0, {%1, %1};" : "=l"(pa) : "r"(__float_as_uint(a)));
            asm("fma.rn.f32x2 %0, %1, %2, %0;" : "+l"(acc[r]) : "l"(pa), "l"(wp));
        }
    }

    int head = lane >> 2;
    int d = (2 * lane) & 7;
#pragma unroll
    for (int r = 0; r < 4; r++) {
        int row = row0 + r0 + r;
        float a0, a1;
        asm("mov.b64 {%0, %1}, %2;" : "=f"(a0), "=f"(a1) : "l"(acc[r]));
        float p0 = a0 * att[head * 8 + d]      + a1 * att[head * 8 + d + 1];
        float p1 = a0 * att[64 + head * 8 + d] + a1 * att[64 + head * 8 + d + 1];
        p0 += __shfl_xor_sync(0xffffffffu, p0, 1);
        p0 += __shfl_xor_sync(0xffffffffu, p0, 2);
        p1 += __shfl_xor_sync(0xffffffffu, p1, 1);
        p1 += __shfl_xor_sync(0xffffffffu, p1, 2);
        if (row < n) {
            ((__half2*)g_hh)[row * 32 + lane] = __floats2half2_rn(a0, a1);
            if ((lane & 3) == 0) {
                g_esrc[row * NH + head] = p0;
                g_edst[row * NH + head] = p1;
            }
        }
    }
}

// ---------------- agg: padded flat 8-batches, direct exp (R13, frozen) ----------------
__global__ void __launch_bounds__(256, 6) agg_kernel(const float* __restrict__ bias,
                           float* __restrict__ xout, int apply_elu, int n) {
    int wg = (blockIdx.x * blockDim.x + threadIdx.x) >> 5;
    int lane = threadIdx.x & 31;
    if (wg >= n) return;
    int head = lane >> 2;
    float ed = g_edst[wg * NH + head];
    int nb = g_end[wg] >> 3;
    const __half2* __restrict__ hh = (const __half2*)g_hh;
    const float* __restrict__ esrc = g_esrc;
    const int4* __restrict__ csrc4 = (const int4*)(g_csrc + wg * CAP);

    float s = 0.f, ax = 0.f, ay = 0.f;

    for (int b = 0; b < nb; b++) {
        int4 c0 = csrc4[2 * b];
        int4 c1 = csrc4[2 * b + 1];
        int v[8] = {c0.x, c0.y, c0.z, c0.w, c1.x, c1.y, c1.z, c1.w};  // 8*src
        float ev[8];
        __half2 hv[8];
#pragma unroll
        for (int j = 0; j < 8; j++) ev[j] = esrc[v[j] + head];
#pragma unroll
        for (int j = 0; j < 8; j++) hv[j] = hh[v[j] * 4 + lane];
#pragma unroll
        for (int j = 0; j < 8; j++) {
            float e = ev[j] + ed;
            e = e > 0.f ? e : 0.2f * e;        // leaky relu
            float p = __expf(e);               // sentinel -> exp(-huge) = 0
            float2 hf = __half22float2(hv[j]);
            s  += p;
            ax = fmaf(p, hf.x, ax);
            ay = fmaf(p, hf.y, ay);
        }
    }

    float inv = 1.f / (s + 1e-16f);
    float o0 = ax * inv + bias[2 * lane];
    float o1 = ay * inv + bias[2 * lane + 1];
    if (apply_elu) {
        o0 = o0 > 0.f ? o0 : expm1f(o0);
        o1 = o1 > 0.f ? o1 : expm1f(o1);
    }
    float* dest = xout ? xout : g_xbuf;
    ((float2*)dest)[wg * 32 + lane] = make_float2(o0, o1);
}

// ---------------- launch ----------------
extern "C" void kernel_launch(void* const* d_in, const int* in_sizes, int n_in,
                              void* d_out, int out_size) {
    const float* x  = (const float*)d_in[0];
    const int*   ei = (const int*)d_in[1];
    int n = in_sizes[0] / 128;
    int e = in_sizes[1] / 2;
    const int* src = ei;
    const int* dst = ei + e;

    const float* W[4], *att[4], *b[4];
    for (int l = 0; l < 4; l++) {
        W[l]   = (const float*)d_in[2 + 3 * l];
        att[l] = (const float*)d_in[3 + 3 * l];
        b[l]   = (const float*)d_in[4 + 3 * l];
    }

    // bucket CSR build
    zero_counts<<<(n + 255) / 256, 256>>>(n);
    fill_buckets<<<(e + 255) / 256, 256>>>(src, dst, e, n);
    pad_buckets<<<(n + 255) / 256, 256>>>(n);

    int gemm_blk = (n + 31) / 32;
    int agg_blk  = (n + 7) / 8;

    gemm_att<128><<<gemm_blk, 256>>>(x, W[0], att[0], n);
    agg_kernel<<<agg_blk, 256>>>(b[0], nullptr, 1, n);
    gemm_att<64><<<gemm_blk, 256>>>(nullptr, W[1], att[1], n);
    agg_kernel<<<agg_blk, 256>>>(b[1], nullptr, 1, n);
    gemm_att<64><<<gemm_blk, 256>>>(nullptr, W[2], att[2], n);
    agg_kernel<<<agg_blk, 256>>>(b[2], nullptr, 1, n);
    gemm_att<64><<<gemm_blk, 256>>>(nullptr, W[3], att[3], n);
    agg_kernel<<<agg_blk, 256>>>(b[3], (float*)d_out, 0, n);
}

// round 17
// speedup vs baseline: 1.8769x; 1.1929x over previous
#include <cuda_runtime.h>
#include <cuda_fp16.h>
#include <math_constants.h>

#define NMAX 50000
#define EMAX 1600000
#define HD 64
#define NH 8
#define CAP 128
#define SENT_VAL -1e30f
#define LOG2E 1.4426950408889634f

typedef unsigned long long u64;

// ---- scratch (static device globals; no allocation allowed) ----
__device__ __align__(16)  __half g_hh[(NMAX + 1) * HD];  // +1 sentinel row (zeros)
__device__ __align__(128) float g_esrc[(NMAX + 1) * NH]; // +1 sentinel row (-1e30), log2e-scaled
__device__ __align__(128) float g_edst[NMAX * NH];       // log2e-scaled
__device__ __align__(16)  float g_xbuf[NMAX * HD];
__device__ int g_end[NMAX];                              // padded end offset per node
__device__ int g_cursor[NMAX];
__device__ __align__(16) int g_csrc[NMAX * CAP];         // buckets, entries pre-scaled by 8

// ---------------- bucket CSR construction ----------------
__global__ void zero_counts(int n) {
    int i = blockIdx.x * blockDim.x + threadIdx.x;
    if (i < n) g_cursor[i] = 0;
    if (blockIdx.x == 0) {
        if (threadIdx.x < NH) g_esrc[n * NH + threadIdx.x] = SENT_VAL;
        if (threadIdx.x < HD) g_hh[n * HD + threadIdx.x] = __float2half(0.f);
    }
}

__global__ void fill_buckets(const int* __restrict__ src, const int* __restrict__ dst,
                             int e, int n) {
    int i = blockIdx.x * blockDim.x + threadIdx.x;
    if (i < e) {
        int d = dst[i];
        int pos = atomicAdd(&g_cursor[d], 1);
        if (pos < CAP) g_csrc[d * CAP + pos] = src[i] * NH;   // pre-scaled index
    }
}

__global__ void pad_buckets(int n) {
    int i = blockIdx.x * blockDim.x + threadIdx.x;
    if (i >= n) return;
    int c = g_cursor[i];
    if (c > CAP) c = CAP;
    int ce = (c + 7) & ~7;
    int sv = n * NH;
    for (int p = c; p < ce; p++) g_csrc[i * CAP + p] = sv;
    g_end[i] = ce;
}

// ---------------- fused GEMM + attention logits (R15, frozen; logits *log2e) ----------------
template <int FIN>
__global__ void gemm_att(const float* __restrict__ xin,
                         const float* __restrict__ W,
                         const float* __restrict__ att, int n) {
    __shared__ float sx[32][FIN];
    int tid = threadIdx.x;

    int row0 = blockIdx.x * 32;
    const float* xp = xin ? xin : g_xbuf;
    for (int i = tid; i < 8 * FIN; i += 256) {
        int r = i / (FIN / 4);
        int kk = (i % (FIN / 4)) * 4;
        float4 v = make_float4(0.f, 0.f, 0.f, 0.f);
        if (row0 + r < n) v = *(const float4*)(xp + (row0 + r) * FIN + kk);
        *(float4*)(&sx[r][kk]) = v;
    }
    __syncthreads();

    int warp = tid >> 5, lane = tid & 31;
    int r0 = warp * 4;
    const u64* __restrict__ W64 = (const u64*)W;

    u64 acc[4] = {0ull, 0ull, 0ull, 0ull};
#pragma unroll 8
    for (int k = 0; k < FIN; k++) {
        u64 wp = __ldg(W64 + k * 32 + lane);
#pragma unroll
        for (int r = 0; r < 4; r++) {
            float a = sx[r0 + r][k];
            u64 pa;
            asm("mov.b64 %0, {%1, %1};" : "=l"(pa) : "r"(__float_as_uint(a)));
            asm("fma.rn.f32x2 %0, %1, %2, %0;" : "+l"(acc[r]) : "l"(pa), "l"(wp));
        }
    }

    int head = lane >> 2;
    int d = (2 * lane) & 7;
#pragma unroll
    for (int r = 0; r < 4; r++) {
        int row = row0 + r0 + r;
        float a0, a1;
        asm("mov.b64 {%0, %1}, %2;" : "=f"(a0), "=f"(a1) : "l"(acc[r]));
        float p0 = a0 * att[head * 8 + d]      + a1 * att[head * 8 + d + 1];
        float p1 = a0 * att[64 + head * 8 + d] + a1 * att[64 + head * 8 + d + 1];
        p0 += __shfl_xor_sync(0xffffffffu, p0, 1);
        p0 += __shfl_xor_sync(0xffffffffu, p0, 2);
        p1 += __shfl_xor_sync(0xffffffffu, p1, 1);
        p1 += __shfl_xor_sync(0xffffffffu, p1, 2);
        if (row < n) {
            ((__half2*)g_hh)[row * 32 + lane] = __floats2half2_rn(a0, a1);
            if ((lane & 3) == 0) {
                g_esrc[row * NH + head] = p0 * LOG2E;   // exp2 trick
                g_edst[row * NH + head] = p1 * LOG2E;
            }
        }
    }
}

// ---------------- agg: 2 dst nodes per warp, 16 lanes/node, 4 dims/lane ----------------
__global__ void __launch_bounds__(256, 6) agg_kernel(const float* __restrict__ bias,
                           float* __restrict__ xout, int apply_elu, int n) {
    int lane = threadIdx.x & 31;
    int l16 = lane & 15;
    int node = ((blockIdx.x * blockDim.x + threadIdx.x) >> 5) * 2 + (lane >> 4);
    if (node >= n) node = n - 1;          // duplicate work, same value -> benign
    int head = l16 >> 1;                  // 2 lanes per head
    int q = l16 & 1;                      // 4-dim group within head

    float ed = g_edst[node * NH + head];
    int nb = g_end[node] >> 3;
    int nbo = __shfl_xor_sync(0xffffffffu, nb, 16);
    int nbmax = max(nb, nbo);
    int sentv = n * NH;

    const uint2* __restrict__ hh2 = (const uint2*)g_hh;   // 4 halves per load; 16 uint2/row
    const float* __restrict__ esrc = g_esrc;
    const int4* __restrict__ csrc4 = (const int4*)(g_csrc + node * CAP);
    int hoff = head * 2 + q;              // uint2 offset within 16-uint2 row

    float s = 0.f;
    float a0 = 0.f, a1 = 0.f, a2 = 0.f, a3 = 0.f;

    for (int b = 0; b < nbmax; b++) {
        int4 c0 = csrc4[2 * b];           // in-bounds (CAP slots); garbage masked below
        int4 c1 = csrc4[2 * b + 1];
        int v[8] = {c0.x, c0.y, c0.z, c0.w, c1.x, c1.y, c1.z, c1.w};
        if (b >= nb) {                    // this half's list exhausted -> all sentinel
#pragma unroll
            for (int j = 0; j < 8; j++) v[j] = sentv;
        }
        float ev[8];
        uint2 hv[8];
#pragma unroll
        for (int j = 0; j < 8; j++) ev[j] = esrc[v[j] + head];
#pragma unroll
        for (int j = 0; j < 8; j++) hv[j] = hh2[v[j] * 2 + hoff];   // row base = 16*src
#pragma unroll
        for (int j = 0; j < 8; j++) {
            float e = ev[j] + ed;
            float p = exp2f(fmaxf(e, 0.2f * e));     // leaky+exp (log2e pre-scaled)
            float2 f0 = __half22float2(*(__half2*)&hv[j].x);
            float2 f1 = __half22float2(*(__half2*)&hv[j].y);
            s += p;
            a0 = fmaf(p, f0.x, a0);
            a1 = fmaf(p, f0.y, a1);
            a2 = fmaf(p, f1.x, a2);
            a3 = fmaf(p, f1.y, a3);
        }
    }

    float inv = 1.f / (s + 1e-16f);
    int dbase = head * 8 + q * 4;
    float o0 = a0 * inv + bias[dbase + 0];
    float o1 = a1 * inv + bias[dbase + 1];
    float o2 = a2 * inv + bias[dbase + 2];
    float o3 = a3 * inv + bias[dbase + 3];
    if (apply_elu) {
        o0 = o0 > 0.f ? o0 : expm1f(o0);
        o1 = o1 > 0.f ? o1 : expm1f(o1);
        o2 = o2 > 0.f ? o2 : expm1f(o2);
        o3 = o3 > 0.f ? o3 : expm1f(o3);
    }
    float* dest = xout ? xout : g_xbuf;
    *(float4*)(dest + node * HD + dbase) = make_float4(o0, o1, o2, o3);
}

// ---------------- launch ----------------
extern "C" void kernel_launch(void* const* d_in, const int* in_sizes, int n_in,
                              void* d_out, int out_size) {
    const float* x  = (const float*)d_in[0];
    const int*   ei = (const int*)d_in[1];
    int n = in_sizes[0] / 128;
    int e = in_sizes[1] / 2;
    const int* src = ei;
    const int* dst = ei + e;

    const float* W[4], *att[4], *b[4];
    for (int l = 0; l < 4; l++) {
        W[l]   = (const float*)d_in[2 + 3 * l];
        att[l] = (const float*)d_in[3 + 3 * l];
        b[l]   = (const float*)d_in[4 + 3 * l];
    }

    // bucket CSR build
    zero_counts<<<(n + 255) / 256, 256>>>(n);
    fill_buckets<<<(e + 255) / 256, 256>>>(src, dst, e, n);
    pad_buckets<<<(n + 255) / 256, 256>>>(n);

    int gemm_blk = (n + 31) / 32;
    int agg_blk  = (n + 15) / 16;         // 16 nodes per 256-thread block

    gemm_att<128><<<gemm_blk, 256>>>(x, W[0], att[0], n);
    agg_kernel<<<agg_blk, 256>>>(b[0], nullptr, 1, n);
    gemm_att<64><<<gemm_blk, 256>>>(nullptr, W[1], att[1], n);
    agg_kernel<<<agg_blk, 256>>>(b[1], nullptr, 1, n);
    gemm_att<64><<<gemm_blk, 256>>>(nullptr, W[2], att[2], n);
    agg_kernel<<<agg_blk, 256>>>(b[2], nullptr, 1, n);
    gemm_att<64><<<gemm_blk, 256>>>(nullptr, W[3], att[3], n);
    agg_kernel<<<agg_blk, 256>>>(b[3], (float*)d_out, 0, n);
}